// round 16
// baseline (speedup 1.0000x reference)
#include <cuda_runtime.h>
#include <cstdint>
#include <math.h>

#define NB   32
#define CIN  2
#define COUT 20
#define PIX  65536
#define RTOT 2097152u
#define NTRI 4

#define OFF_VIS   4194304u
#define OFF_MUHID 8388608u
#define OFF_HID   50331648u

struct Params { unsigned k[8]; };   // per step: k1 (a,b), k2 (a,b)

// ---------------------------------------------------------------------------
// Threefry-2x32 (20 rounds) -- JAX partitionable, counter-high == 0
// ---------------------------------------------------------------------------
#define TF_R(x0, x1, r) { x0 += x1; x1 = __funnelshift_l(x1, x1, r); x1 ^= x0; }

__device__ __forceinline__ unsigned tf_xor(unsigned k0, unsigned k1, unsigned lo) {
    unsigned ks2 = k0 ^ k1 ^ 0x1BD11BDAu;
    unsigned x0 = k0;
    unsigned x1 = lo + k1;
    TF_R(x0,x1,13) TF_R(x0,x1,15) TF_R(x0,x1,26) TF_R(x0,x1,6)
    x0 += k1;  x1 += ks2 + 1u;
    TF_R(x0,x1,17) TF_R(x0,x1,29) TF_R(x0,x1,16) TF_R(x0,x1,24)
    x0 += ks2; x1 += k0 + 2u;
    TF_R(x0,x1,13) TF_R(x0,x1,15) TF_R(x0,x1,26) TF_R(x0,x1,6)
    x0 += k0;  x1 += k1 + 3u;
    TF_R(x0,x1,17) TF_R(x0,x1,29) TF_R(x0,x1,16) TF_R(x0,x1,24)
    x0 += k1;  x1 += ks2 + 4u;
    TF_R(x0,x1,13) TF_R(x0,x1,15) TF_R(x0,x1,26) TF_R(x0,x1,6)
    x0 += ks2; x1 += k0 + 5u;
    return x0 ^ x1;
}

__device__ __forceinline__ float u01(unsigned k0, unsigned k1, unsigned idx) {
    unsigned bits = tf_xor(k0, k1, idx);
    return __uint_as_float((bits >> 9) | 0x3f800000u) - 1.0f;
}

// PROVEN flip-free sigmoid (output 1 == 0.0, R1-R15). Do not touch.
__device__ __forceinline__ float xla_sigmoid(float x) {
    return __fdiv_rn(1.0f, 1.0f + expf(-x));
}

// PROVEN exp (out2 == 0.0 in R11-R15)
__device__ __forceinline__ float cephes_expf_fused(float x) {
    float m = floorf(__fmaf_rn(x, 1.44269504088896341f, 0.5f));
    float r = __fmaf_rn(m, -0.693359375f, x);
    r = __fmaf_rn(m, 2.12194440e-4f, r);
    float r2 = __fmul_rn(r, r);
    float y = __fmaf_rn(1.9875691500E-4f, r, 1.3981999507E-3f);
    y = __fmaf_rn(y, r, 8.3334519073E-3f);
    y = __fmaf_rn(y, r, 4.1665795894E-2f);
    y = __fmaf_rn(y, r, 1.6666665459E-1f);
    y = __fmaf_rn(y, r, 5.0000001201E-1f);
    y = __fmaf_rn(y, r2, r);
    y = __fadd_rn(y, 1.0f);
    float s = __int_as_float(((int)m + 127) << 23);
    return __fmul_rn(y, s);
}

// ---------------------------------------------------------------------------
// Fused 2-step CD kernel. PROVEN-exact arithmetic (R12/R14/R15).
// NEW: __launch_bounds__(256, 6) caps regs at 40 => 6 blocks/SM = 75% occ.
// The a[]-free R15 dataflow gives ptxas slack to meet the cap w/o spills.
// ---------------------------------------------------------------------------
__global__ void __launch_bounds__(256, 6)
cd_fused_kernel(const float* __restrict__ hid_in,
                const float* __restrict__ Wp,      // (20,2)
                const float* __restrict__ bvis,    // (2,)
                const float* __restrict__ bhid,    // (20,)
                float* __restrict__ out,
                Params prm)
{
    __shared__ float sW[COUT * 2];
    __shared__ float sBv[CIN];
    __shared__ float sProb[4 * COUT];
    __shared__ float sCdf[4 * COUT];
    if (threadIdx.x < COUT * 2) sW[threadIdx.x] = Wp[threadIdx.x];
    if (threadIdx.x < CIN)      sBv[threadIdx.x] = bvis[threadIdx.x];
    __syncthreads();

    if (threadIdx.x < 4) {
        int c = threadIdx.x;
        float v0 = (float)(c & 1);
        float v1 = (float)((c >> 1) & 1);
        float e[COUT];
        #pragma unroll
        for (int o = 0; o < COUT; o++) {
            float acc = __fmul_rn(sW[2*o+0], v0);
            acc = __fadd_rn(acc, __fmul_rn(sW[2*o+1], v1));
            e[o] = __fadd_rn(acc, bhid[o]);           // b_hid == 0, exact
        }
        float m = e[0];
        #pragma unroll
        for (int o = 1; o < COUT; o++) m = fmaxf(m, e[o]);
        #pragma unroll
        for (int o = 0; o < COUT; o++) e[o] = cephes_expf_fused(__fsub_rn(e[o], m));

        float S = 0.0f;
        #pragma unroll
        for (int o = 0; o < COUT; o++) S = __fadd_rn(S, e[o]);

        float rcp = __fdiv_rn(1.0f, S);
        float run = 0.0f;
        #pragma unroll
        for (int o = 0; o < COUT; o++) {
            float pr = __fmul_rn(e[o], rcp);
            sProb[c * COUT + o] = pr;
            run = __fadd_rn(run, pr);                 // SEQUENTIAL cumsum (proven)
            sCdf[c * COUT + o] = run;
        }
    }
    __syncthreads();

    unsigned r = blockIdx.x * 256u + threadIdx.x;
    unsigned n = r >> 16;
    unsigned p = r & 0xFFFFu;

    // step-0 emit dot straight from global hid (no a[] buffer)
    float e0 = 0.0f, e1 = 0.0f;
    {
        const float* hp = hid_in + (size_t)n * (COUT * PIX) + p;
        #pragma unroll
        for (int o = 0; o < COUT; o++) {
            float h = hp[(size_t)o << 16];
            e0 = fmaf(h, sW[2*o+0], e0);
            e1 = fmaf(h, sW[2*o+1], e1);
        }
        e0 += sBv[0]; e1 += sBv[1];
    }

    #pragma unroll
    for (int step = 0; step < 2; step++) {
        const unsigned k1a = prm.k[step*4+0], k1b = prm.k[step*4+1];
        const unsigned k2a = prm.k[step*4+2], k2b = prm.k[step*4+3];

        float muv0 = xla_sigmoid(e0);
        float muv1 = xla_sigmoid(e1);
        float uu0 = u01(k1a, k1b, (n * 2u + 0u) * (unsigned)PIX + p);
        float uu1 = u01(k1a, k1b, (n * 2u + 1u) * (unsigned)PIX + p);
        int iv0 = (uu0 < muv0) ? 1 : 0;
        int iv1 = (uu1 < muv1) ? 1 : 0;

        if (step == 1) {
            out[(size_t)((n*2u+0u) << 16) + p]           = muv0;
            out[(size_t)((n*2u+1u) << 16) + p]           = muv1;
            out[(size_t)OFF_VIS + ((n*2u+0u) << 16) + p] = (float)iv0;
            out[(size_t)OFF_VIS + ((n*2u+1u) << 16) + p] = (float)iv1;
        }

        int cb = iv0 + 2 * iv1;
        const float* cdf = &sCdf[cb * COUT];

        if (step == 1) {
            const float* pb = &sProb[cb * COUT];
            size_t base = (size_t)OFF_MUHID + (((size_t)n * COUT) << 16) + p;
            #pragma unroll
            for (int o = 0; o < COUT; o++)
                out[base + ((size_t)o << 16)] = 4.0f * pb[o];
        }

        unsigned jb = r * 4u;
        float U0 = u01(k2a, k2b, jb + 0u);
        float U1 = u01(k2a, k2b, jb + 1u);
        float U2 = u01(k2a, k2b, jb + 2u);
        float U3 = u01(k2a, k2b, jb + 3u);

        // counting searchsorted fused with next-emit fmaf chain / final store.
        size_t hbase = (size_t)OFF_HID + (((size_t)n * COUT) << 16) + p;
        int prev = NTRI;
        float ne0 = 0.0f, ne1 = 0.0f;
        #pragma unroll
        for (int c = 1; c < COUT; c++) {
            float b = cdf[c-1];
            int Ac = (int)(b < U0) + (int)(b < U1)
                   + (int)(b < U2) + (int)(b < U3);
            float f = (float)(prev - Ac);
            prev = Ac;
            if (step == 0) {
                ne0 = fmaf(f, sW[2*(c-1)+0], ne0);
                ne1 = fmaf(f, sW[2*(c-1)+1], ne1);
            } else {
                out[hbase + ((size_t)(c-1) << 16)] = f;
            }
        }
        {
            float f = (float)prev;
            if (step == 0) {
                ne0 = fmaf(f, sW[2*(COUT-1)+0], ne0);
                ne1 = fmaf(f, sW[2*(COUT-1)+1], ne1);
                e0 = ne0 + sBv[0];
                e1 = ne1 + sBv[1];
            } else {
                out[hbase + ((size_t)(COUT-1) << 16)] = f;
            }
        }
    }
}

// ---------------------------------------------------------------------------
// Host-side threefry for key derivation (pure constants)
// ---------------------------------------------------------------------------
#define TFH_R(x0, x1, r) { x0 += x1; x1 = (x1 << (r)) | (x1 >> (32 - (r))); x1 ^= x0; }
static void tf_pair_host(unsigned k0, unsigned k1, unsigned hi, unsigned lo,
                         unsigned* o0, unsigned* o1) {
    unsigned ks2 = k0 ^ k1 ^ 0x1BD11BDAu;
    unsigned x0 = hi + k0;
    unsigned x1 = lo + k1;
    TFH_R(x0,x1,13) TFH_R(x0,x1,15) TFH_R(x0,x1,26) TFH_R(x0,x1,6)
    x0 += k1;  x1 += ks2 + 1u;
    TFH_R(x0,x1,17) TFH_R(x0,x1,29) TFH_R(x0,x1,16) TFH_R(x0,x1,24)
    x0 += ks2; x1 += k0 + 2u;
    TFH_R(x0,x1,13) TFH_R(x0,x1,15) TFH_R(x0,x1,26) TFH_R(x0,x1,6)
    x0 += k0;  x1 += k1 + 3u;
    TFH_R(x0,x1,17) TFH_R(x0,x1,29) TFH_R(x0,x1,16) TFH_R(x0,x1,24)
    x0 += k1;  x1 += ks2 + 4u;
    TFH_R(x0,x1,13) TFH_R(x0,x1,15) TFH_R(x0,x1,26) TFH_R(x0,x1,6)
    x0 += ks2; x1 += k0 + 5u;
    *o0 = x0; *o1 = x1;
}

extern "C" void kernel_launch(void* const* d_in, const int* in_sizes, int n_in,
                              void* d_out, int out_size) {
    const float* hid  = (const float*)d_in[0];
    const float* Wp   = (const float*)d_in[1];
    const float* bvis = (const float*)d_in[2];
    const float* bhid = (const float*)d_in[3];
    float* out = (float*)d_out;

    Params prm;
    for (int s = 0; s < 2; s++) {
        unsigned ka, kb;
        tf_pair_host(0u, 42u, 0u, (unsigned)s, &ka, &kb);
        unsigned k1a, k1b, k2a, k2b;
        tf_pair_host(ka, kb, 0u, 0u, &k1a, &k1b);
        tf_pair_host(ka, kb, 0u, 1u, &k2a, &k2b);
        prm.k[s*4+0] = k1a; prm.k[s*4+1] = k1b;
        prm.k[s*4+2] = k2a; prm.k[s*4+3] = k2b;
    }

    dim3 grid(RTOT / 256u);
    cd_fused_kernel<<<grid, 256>>>(hid, Wp, bvis, bhid, out, prm);
}

// round 17
// speedup vs baseline: 1.1122x; 1.1122x over previous
#include <cuda_runtime.h>
#include <cstdint>
#include <math.h>

#define NB   32
#define CIN  2
#define COUT 20
#define PIX  65536
#define RTOT 2097152u
#define NTRI 4

#define OFF_VIS   4194304u
#define OFF_MUHID 8388608u
#define OFF_HID   50331648u

struct Params { unsigned k[8]; };   // per step: k1 (a,b), k2 (a,b)

// ---------------------------------------------------------------------------
// Threefry-2x32 (20 rounds) -- JAX partitionable, counter-high == 0
// ---------------------------------------------------------------------------
#define TF_R(x0, x1, r) { x0 += x1; x1 = __funnelshift_l(x1, x1, r); x1 ^= x0; }

__device__ __forceinline__ unsigned tf_xor(unsigned k0, unsigned k1, unsigned lo) {
    unsigned ks2 = k0 ^ k1 ^ 0x1BD11BDAu;
    unsigned x0 = k0;
    unsigned x1 = lo + k1;
    TF_R(x0,x1,13) TF_R(x0,x1,15) TF_R(x0,x1,26) TF_R(x0,x1,6)
    x0 += k1;  x1 += ks2 + 1u;
    TF_R(x0,x1,17) TF_R(x0,x1,29) TF_R(x0,x1,16) TF_R(x0,x1,24)
    x0 += ks2; x1 += k0 + 2u;
    TF_R(x0,x1,13) TF_R(x0,x1,15) TF_R(x0,x1,26) TF_R(x0,x1,6)
    x0 += k0;  x1 += k1 + 3u;
    TF_R(x0,x1,17) TF_R(x0,x1,29) TF_R(x0,x1,16) TF_R(x0,x1,24)
    x0 += k1;  x1 += ks2 + 4u;
    TF_R(x0,x1,13) TF_R(x0,x1,15) TF_R(x0,x1,26) TF_R(x0,x1,6)
    x0 += ks2; x1 += k0 + 5u;
    return x0 ^ x1;
}

__device__ __forceinline__ float u01(unsigned k0, unsigned k1, unsigned idx) {
    unsigned bits = tf_xor(k0, k1, idx);
    return __uint_as_float((bits >> 9) | 0x3f800000u) - 1.0f;
}

// PROVEN flip-free sigmoid (output 1 == 0.0, R1-R16). Do not touch.
__device__ __forceinline__ float xla_sigmoid(float x) {
    return __fdiv_rn(1.0f, 1.0f + expf(-x));
}

// PROVEN exp (out2 == 0.0 in R11-R16)
__device__ __forceinline__ float cephes_expf_fused(float x) {
    float m = floorf(__fmaf_rn(x, 1.44269504088896341f, 0.5f));
    float r = __fmaf_rn(m, -0.693359375f, x);
    r = __fmaf_rn(m, 2.12194440e-4f, r);
    float r2 = __fmul_rn(r, r);
    float y = __fmaf_rn(1.9875691500E-4f, r, 1.3981999507E-3f);
    y = __fmaf_rn(y, r, 8.3334519073E-3f);
    y = __fmaf_rn(y, r, 4.1665795894E-2f);
    y = __fmaf_rn(y, r, 1.6666665459E-1f);
    y = __fmaf_rn(y, r, 5.0000001201E-1f);
    y = __fmaf_rn(y, r2, r);
    y = __fadd_rn(y, 1.0f);
    float s = __int_as_float(((int)m + 127) << 23);
    return __fmul_rn(y, s);
}

// ---------------------------------------------------------------------------
// Fused 2-step CD kernel, TWO pixels per thread (lockstep) for 2x ILP and
// 64-bit loads/stores. Per-pixel arithmetic bit-identical to R12/R15.
// ---------------------------------------------------------------------------
__global__ void __launch_bounds__(256)
cd_fused_kernel(const float* __restrict__ hid_in,
                const float* __restrict__ Wp,      // (20,2)
                const float* __restrict__ bvis,    // (2,)
                const float* __restrict__ bhid,    // (20,)
                float* __restrict__ out,
                Params prm)
{
    __shared__ float sW[COUT * 2];
    __shared__ float sBv[CIN];
    __shared__ float sProb[4 * COUT];
    __shared__ float sCdf[4 * COUT];
    if (threadIdx.x < COUT * 2) sW[threadIdx.x] = Wp[threadIdx.x];
    if (threadIdx.x < CIN)      sBv[threadIdx.x] = bvis[threadIdx.x];
    __syncthreads();

    if (threadIdx.x < 4) {
        int c = threadIdx.x;
        float v0 = (float)(c & 1);
        float v1 = (float)((c >> 1) & 1);
        float e[COUT];
        #pragma unroll
        for (int o = 0; o < COUT; o++) {
            float acc = __fmul_rn(sW[2*o+0], v0);
            acc = __fadd_rn(acc, __fmul_rn(sW[2*o+1], v1));
            e[o] = __fadd_rn(acc, bhid[o]);           // b_hid == 0, exact
        }
        float m = e[0];
        #pragma unroll
        for (int o = 1; o < COUT; o++) m = fmaxf(m, e[o]);
        #pragma unroll
        for (int o = 0; o < COUT; o++) e[o] = cephes_expf_fused(__fsub_rn(e[o], m));

        float S = 0.0f;
        #pragma unroll
        for (int o = 0; o < COUT; o++) S = __fadd_rn(S, e[o]);

        float rcp = __fdiv_rn(1.0f, S);
        float run = 0.0f;
        #pragma unroll
        for (int o = 0; o < COUT; o++) {
            float pr = __fmul_rn(e[o], rcp);
            sProb[c * COUT + o] = pr;
            run = __fadd_rn(run, pr);                 // SEQUENTIAL cumsum (proven)
            sCdf[c * COUT + o] = run;
        }
    }
    __syncthreads();

    unsigned r0 = (blockIdx.x * 256u + threadIdx.x) * 2u;   // even pixel row
    unsigned n = r0 >> 16;
    unsigned p = r0 & 0xFFFFu;        // even; p+1 stays within same n

    // step-0 emit dot for both pixels (float2 loads)
    float e0a = 0.0f, e1a = 0.0f, e0b = 0.0f, e1b = 0.0f;
    {
        const float* hp = hid_in + (size_t)n * (COUT * PIX) + p;
        #pragma unroll
        for (int o = 0; o < COUT; o++) {
            float2 h = *reinterpret_cast<const float2*>(&hp[(size_t)o << 16]);
            e0a = fmaf(h.x, sW[2*o+0], e0a);
            e1a = fmaf(h.x, sW[2*o+1], e1a);
            e0b = fmaf(h.y, sW[2*o+0], e0b);
            e1b = fmaf(h.y, sW[2*o+1], e1b);
        }
        e0a += sBv[0]; e1a += sBv[1];
        e0b += sBv[0]; e1b += sBv[1];
    }

    #pragma unroll
    for (int step = 0; step < 2; step++) {
        const unsigned k1a = prm.k[step*4+0], k1b = prm.k[step*4+1];
        const unsigned k2a = prm.k[step*4+2], k2b = prm.k[step*4+3];

        float mva0 = xla_sigmoid(e0a);
        float mva1 = xla_sigmoid(e1a);
        float mvb0 = xla_sigmoid(e0b);
        float mvb1 = xla_sigmoid(e1b);
        unsigned cb0 = (n << 17) + p;            // (2n)*PIX + p
        float ua0 = u01(k1a, k1b, cb0);
        float ub0 = u01(k1a, k1b, cb0 + 1u);
        float ua1 = u01(k1a, k1b, cb0 + PIX);
        float ub1 = u01(k1a, k1b, cb0 + PIX + 1u);
        int iva0 = (ua0 < mva0) ? 1 : 0;
        int iva1 = (ua1 < mva1) ? 1 : 0;
        int ivb0 = (ub0 < mvb0) ? 1 : 0;
        int ivb1 = (ub1 < mvb1) ? 1 : 0;

        if (step == 1) {
            *reinterpret_cast<float2*>(&out[(size_t)((n*2u+0u) << 16) + p]) =
                make_float2(mva0, mvb0);
            *reinterpret_cast<float2*>(&out[(size_t)((n*2u+1u) << 16) + p]) =
                make_float2(mva1, mvb1);
            *reinterpret_cast<float2*>(&out[(size_t)OFF_VIS + ((n*2u+0u) << 16) + p]) =
                make_float2((float)iva0, (float)ivb0);
            *reinterpret_cast<float2*>(&out[(size_t)OFF_VIS + ((n*2u+1u) << 16) + p]) =
                make_float2((float)iva1, (float)ivb1);
        }

        int cbA = iva0 + 2 * iva1;
        int cbB = ivb0 + 2 * ivb1;
        const float* cdfA = &sCdf[cbA * COUT];
        const float* cdfB = &sCdf[cbB * COUT];

        if (step == 1) {
            const float* pA = &sProb[cbA * COUT];
            const float* pB = &sProb[cbB * COUT];
            size_t base = (size_t)OFF_MUHID + (((size_t)n * COUT) << 16) + p;
            #pragma unroll
            for (int o = 0; o < COUT; o++)
                *reinterpret_cast<float2*>(&out[base + ((size_t)o << 16)]) =
                    make_float2(4.0f * pA[o], 4.0f * pB[o]);
        }

        unsigned jbA = r0 * 4u;
        unsigned jbB = jbA + 4u;
        float UA0 = u01(k2a, k2b, jbA + 0u);
        float UA1 = u01(k2a, k2b, jbA + 1u);
        float UA2 = u01(k2a, k2b, jbA + 2u);
        float UA3 = u01(k2a, k2b, jbA + 3u);
        float UB0 = u01(k2a, k2b, jbB + 0u);
        float UB1 = u01(k2a, k2b, jbB + 1u);
        float UB2 = u01(k2a, k2b, jbB + 2u);
        float UB3 = u01(k2a, k2b, jbB + 3u);

        // lockstep counting searchsorted; feeds fmaf chain (step 0) or
        // float2 stores (step 1). Per-pixel order identical to reference.
        size_t hbase = (size_t)OFF_HID + (((size_t)n * COUT) << 16) + p;
        int prevA = NTRI, prevB = NTRI;
        float nA0 = 0.0f, nA1 = 0.0f, nB0 = 0.0f, nB1 = 0.0f;
        #pragma unroll
        for (int c = 1; c < COUT; c++) {
            float bA = cdfA[c-1];
            float bB = cdfB[c-1];
            int AcA = (int)(bA < UA0) + (int)(bA < UA1)
                    + (int)(bA < UA2) + (int)(bA < UA3);
            int AcB = (int)(bB < UB0) + (int)(bB < UB1)
                    + (int)(bB < UB2) + (int)(bB < UB3);
            float fA = (float)(prevA - AcA);
            float fB = (float)(prevB - AcB);
            prevA = AcA; prevB = AcB;
            if (step == 0) {
                nA0 = fmaf(fA, sW[2*(c-1)+0], nA0);
                nA1 = fmaf(fA, sW[2*(c-1)+1], nA1);
                nB0 = fmaf(fB, sW[2*(c-1)+0], nB0);
                nB1 = fmaf(fB, sW[2*(c-1)+1], nB1);
            } else {
                *reinterpret_cast<float2*>(&out[hbase + ((size_t)(c-1) << 16)]) =
                    make_float2(fA, fB);
            }
        }
        {
            float fA = (float)prevA;
            float fB = (float)prevB;
            if (step == 0) {
                nA0 = fmaf(fA, sW[2*(COUT-1)+0], nA0);
                nA1 = fmaf(fA, sW[2*(COUT-1)+1], nA1);
                nB0 = fmaf(fB, sW[2*(COUT-1)+0], nB0);
                nB1 = fmaf(fB, sW[2*(COUT-1)+1], nB1);
                e0a = nA0 + sBv[0];
                e1a = nA1 + sBv[1];
                e0b = nB0 + sBv[0];
                e1b = nB1 + sBv[1];
            } else {
                *reinterpret_cast<float2*>(&out[hbase + ((size_t)(COUT-1) << 16)]) =
                    make_float2(fA, fB);
            }
        }
    }
}

// ---------------------------------------------------------------------------
// Host-side threefry for key derivation (pure constants)
// ---------------------------------------------------------------------------
#define TFH_R(x0, x1, r) { x0 += x1; x1 = (x1 << (r)) | (x1 >> (32 - (r))); x1 ^= x0; }
static void tf_pair_host(unsigned k0, unsigned k1, unsigned hi, unsigned lo,
                         unsigned* o0, unsigned* o1) {
    unsigned ks2 = k0 ^ k1 ^ 0x1BD11BDAu;
    unsigned x0 = hi + k0;
    unsigned x1 = lo + k1;
    TFH_R(x0,x1,13) TFH_R(x0,x1,15) TFH_R(x0,x1,26) TFH_R(x0,x1,6)
    x0 += k1;  x1 += ks2 + 1u;
    TFH_R(x0,x1,17) TFH_R(x0,x1,29) TFH_R(x0,x1,16) TFH_R(x0,x1,24)
    x0 += ks2; x1 += k0 + 2u;
    TFH_R(x0,x1,13) TFH_R(x0,x1,15) TFH_R(x0,x1,26) TFH_R(x0,x1,6)
    x0 += k0;  x1 += k1 + 3u;
    TFH_R(x0,x1,17) TFH_R(x0,x1,29) TFH_R(x0,x1,16) TFH_R(x0,x1,24)
    x0 += k1;  x1 += ks2 + 4u;
    TFH_R(x0,x1,13) TFH_R(x0,x1,15) TFH_R(x0,x1,26) TFH_R(x0,x1,6)
    x0 += ks2; x1 += k0 + 5u;
    *o0 = x0; *o1 = x1;
}

extern "C" void kernel_launch(void* const* d_in, const int* in_sizes, int n_in,
                              void* d_out, int out_size) {
    const float* hid  = (const float*)d_in[0];
    const float* Wp   = (const float*)d_in[1];
    const float* bvis = (const float*)d_in[2];
    const float* bhid = (const float*)d_in[3];
    float* out = (float*)d_out;

    Params prm;
    for (int s = 0; s < 2; s++) {
        unsigned ka, kb;
        tf_pair_host(0u, 42u, 0u, (unsigned)s, &ka, &kb);
        unsigned k1a, k1b, k2a, k2b;
        tf_pair_host(ka, kb, 0u, 0u, &k1a, &k1b);
        tf_pair_host(ka, kb, 0u, 1u, &k2a, &k2b);
        prm.k[s*4+0] = k1a; prm.k[s*4+1] = k1b;
        prm.k[s*4+2] = k2a; prm.k[s*4+3] = k2b;
    }

    dim3 grid(RTOT / 512u);     // 2 pixels per thread
    cd_fused_kernel<<<grid, 256>>>(hid, Wp, bvis, bhid, out, prm);
}